// round 3
// baseline (speedup 1.0000x reference)
#include <cuda_runtime.h>
#include <math.h>

// FinancialPINN: Fourier-feature SIREN with residual blocks + periodic skips.
// Fully fused: one CTA processes a tile of 64 points through the entire
// network, keeping activations (transposed, [feature][point]) in shared
// memory and streaming each layer's weights into a shared 128x128 tile.
// Inner GEMM loops use packed fma.rn.f32x2 (FFMA2) for 2x fp32 throughput.

static constexpr int Fdim    = 128;   // Fourier features per trig fn
static constexpr int Hdim    = 128;   // hidden width
static constexpr int Ldim    = 8;     // residual blocks
static constexpr int MT      = 64;    // points per CTA
static constexpr int THREADS = 256;
static constexpr float OMEGA = 30.0f;

// shared layout (floats)
static constexpr int FF_OFF  = 0;                    // ff  [256][64]
static constexpr int XS_OFF  = FF_OFF + 2*Fdim*MT;   // Xs  [128][64]
static constexpr int HS_OFF  = XS_OFF + Hdim*MT;     // Hs  [128][64]
static constexpr int WS_OFF  = HS_OFF + Hdim*MT;     // Ws  [128][128]
static constexpr int SMEM_FLOATS = WS_OFF + Hdim*Hdim;  // 49152 floats = 192KB

typedef unsigned long long ull;

__device__ __forceinline__ ull pack2(float a) {
    ull r; asm("mov.b64 %0, {%1, %1};" : "=l"(r) : "f"(a)); return r;
}
__device__ __forceinline__ void unpack2(ull v, float& lo, float& hi) {
    asm("mov.b64 {%0, %1}, %2;" : "=f"(lo), "=f"(hi) : "l"(v));
}
__device__ __forceinline__ void fma2(ull& acc, ull x, ull w) {
    asm("fma.rn.f32x2 %0, %1, %2, %0;" : "+l"(acc) : "l"(x), "l"(w));
}

// Load a 128x128 f32 weight tile (contiguous in gmem) into Ws.
__device__ __forceinline__ void loadW(float* Ws, const float* __restrict__ g, int tid) {
    float4*       d = reinterpret_cast<float4*>(Ws);
    const float4* s = reinterpret_cast<const float4*>(g);
#pragma unroll
    for (int i = 0; i < 16; i++) d[tid + i * THREADS] = s[tid + i * THREADS];
}

// acc[mi][nj] (+)= A^T-tile @ W-tile.
// A: [K][MT] in smem (feature-major), W: [K][128] in smem.
// Thread (tx,ty): m = tx*4..tx*4+3, n = ty*8..ty*8+7 (as 4 packed pairs).
__device__ __forceinline__ void gemm_acc(const float* __restrict__ A,
                                         const float* __restrict__ W,
                                         int K, ull acc[4][4], int tx, int ty) {
    const float* a = A + tx * 4;
    const float* w = W + ty * 8;
#pragma unroll 8
    for (int k = 0; k < K; k++) {
        float4 xv = *reinterpret_cast<const float4*>(a);
        ulonglong2 w01 = *reinterpret_cast<const ulonglong2*>(w);
        ulonglong2 w23 = *reinterpret_cast<const ulonglong2*>(w + 4);
        a += MT;
        w += Hdim;
        ull xb0 = pack2(xv.x), xb1 = pack2(xv.y), xb2 = pack2(xv.z), xb3 = pack2(xv.w);
        ull wv0 = w01.x, wv1 = w01.y, wv2 = w23.x, wv3 = w23.y;
        fma2(acc[0][0], xb0, wv0); fma2(acc[0][1], xb0, wv1);
        fma2(acc[0][2], xb0, wv2); fma2(acc[0][3], xb0, wv3);
        fma2(acc[1][0], xb1, wv0); fma2(acc[1][1], xb1, wv1);
        fma2(acc[1][2], xb1, wv2); fma2(acc[1][3], xb1, wv3);
        fma2(acc[2][0], xb2, wv0); fma2(acc[2][1], xb2, wv1);
        fma2(acc[2][2], xb2, wv2); fma2(acc[2][3], xb2, wv3);
        fma2(acc[3][0], xb3, wv0); fma2(acc[3][1], xb3, wv1);
        fma2(acc[3][2], xb3, wv2); fma2(acc[3][3], xb3, wv3);
    }
}

__device__ __forceinline__ void zero_acc(ull acc[4][4]) {
#pragma unroll
    for (int i = 0; i < 4; i++)
#pragma unroll
        for (int j = 0; j < 4; j++) acc[i][j] = 0ULL;
}

extern __shared__ float smem[];

__global__ void __launch_bounds__(THREADS, 1)
pinn_kernel(const float* __restrict__ S,   const float* __restrict__ T,
            const float* __restrict__ B,
            const float* __restrict__ in_w, const float* __restrict__ in_b,
            const float* __restrict__ w1,   const float* __restrict__ b1,
            const float* __restrict__ w2,   const float* __restrict__ b2,
            const float* __restrict__ skw,  const float* __restrict__ skb,
            const float* __restrict__ ow,   const float* __restrict__ ob,
            float* __restrict__ out, int N) {
    float* ff = smem + FF_OFF;   // [2F][MT]
    float* Xs = smem + XS_OFF;   // [H][MT]
    float* Hs = smem + HS_OFF;   // [H][MT]
    float* Ws = smem + WS_OFF;   // [128][128]

    const int tid  = threadIdx.x;
    const int tx   = tid & 15;        // m direction
    const int ty   = tid >> 4;        // n direction
    const int mb   = tx * 4;
    const int nb   = ty * 8;
    const int base = blockIdx.x * MT;

    // ---- stage S,t for this tile into smem (reuse Hs as scratch) ----
    if (tid < MT) {
        int gm = base + tid;
        Hs[tid]      = (gm < N) ? S[gm] : 0.0f;
        Hs[MT + tid] = (gm < N) ? T[gm] : 0.0f;
    }
    __syncthreads();

    // ---- Fourier features: ff[f][m] = sin(proj), ff[F+f][m] = cos(proj) ----
#pragma unroll
    for (int i = 0; i < (2 * Fdim * MT / 2) / THREADS; i++) {   // 8192 (f,m) pairs / 256
        int e = tid + i * THREADS;
        int m = e & (MT - 1);
        int f = e >> 6;
        float proj = Hs[m] * B[f] + Hs[MT + m] * B[Fdim + f];
        float sn, cs;
        sincosf(proj, &sn, &cs);
        ff[f * MT + m]          = sn;
        ff[(f + Fdim) * MT + m] = cs;
    }
    __syncthreads();

    ull acc[4][4];

    // ---- input layer: x = sin(OMEGA * (ff @ in_w + in_b)), K = 256 ----
    zero_acc(acc);
    loadW(Ws, in_w, tid);
    __syncthreads();
    gemm_acc(ff, Ws, Fdim, acc, tx, ty);
    __syncthreads();
    loadW(Ws, in_w + Fdim * Hdim, tid);
    __syncthreads();
    gemm_acc(ff + Fdim * MT, Ws, Fdim, acc, tx, ty);
#pragma unroll
    for (int nj = 0; nj < 4; nj++) {
        float2 bb = *reinterpret_cast<const float2*>(in_b + nb + 2 * nj);
#pragma unroll
        for (int mi = 0; mi < 4; mi++) {
            float v0, v1; unpack2(acc[mi][nj], v0, v1);
            Xs[(nb + 2 * nj) * MT + mb + mi]     = sinf(OMEGA * (v0 + bb.x));
            Xs[(nb + 2 * nj + 1) * MT + mb + mi] = sinf(OMEGA * (v1 + bb.y));
        }
    }
    __syncthreads();

    // ---- residual blocks ----
    for (int layer = 0; layer < Ldim; layer++) {
        // h = tanh(x @ w1 + b1)
        loadW(Ws, w1 + layer * Hdim * Hdim, tid);
        __syncthreads();
        zero_acc(acc);
        gemm_acc(Xs, Ws, Hdim, acc, tx, ty);
#pragma unroll
        for (int nj = 0; nj < 4; nj++) {
            float2 bb = *reinterpret_cast<const float2*>(b1 + layer * Hdim + nb + 2 * nj);
#pragma unroll
            for (int mi = 0; mi < 4; mi++) {
                float v0, v1; unpack2(acc[mi][nj], v0, v1);
                Hs[(nb + 2 * nj) * MT + mb + mi]     = tanhf(v0 + bb.x);
                Hs[(nb + 2 * nj + 1) * MT + mb + mi] = tanhf(v1 + bb.y);
            }
        }
        __syncthreads();

        // acc = h @ w2   (b2 added at the end)
        loadW(Ws, w2 + layer * Hdim * Hdim, tid);
        __syncthreads();
        zero_acc(acc);
        gemm_acc(Hs, Ws, Hdim, acc, tx, ty);

        bool has_skip = ((layer & 1) == 0);
        if (has_skip) {
            // acc += ff @ skip_w[layer/2], K = 256 streamed as 2 chunks
            const float* sw = skw + (layer / 2) * (2 * Fdim) * Hdim;
            __syncthreads();               // gemm done reading Ws
            loadW(Ws, sw, tid);
            __syncthreads();
            gemm_acc(ff, Ws, Fdim, acc, tx, ty);
            __syncthreads();
            loadW(Ws, sw + Fdim * Hdim, tid);
            __syncthreads();
            gemm_acc(ff + Fdim * MT, Ws, Fdim, acc, tx, ty);
        }

        // x += acc + b2 (+ skip_b)
#pragma unroll
        for (int nj = 0; nj < 4; nj++) {
            float2 b2v = *reinterpret_cast<const float2*>(b2 + layer * Hdim + nb + 2 * nj);
            float2 sbv = make_float2(0.0f, 0.0f);
            if (has_skip)
                sbv = *reinterpret_cast<const float2*>(skb + (layer / 2) * Hdim + nb + 2 * nj);
#pragma unroll
            for (int mi = 0; mi < 4; mi++) {
                float v0, v1; unpack2(acc[mi][nj], v0, v1);
                Xs[(nb + 2 * nj) * MT + mb + mi]     += v0 + b2v.x + sbv.x;
                Xs[(nb + 2 * nj + 1) * MT + mb + mi] += v1 + b2v.y + sbv.y;
            }
        }
        __syncthreads();
    }

    // ---- output layer: out = x @ out_w + out_b ----
    if (tid < Hdim) Hs[tid] = ow[tid];     // Hs reused as out_w stage
    __syncthreads();
    if (tid < MT) {
        int gm = base + tid;
        if (gm < N) {
            float s = ob[0];
#pragma unroll 8
            for (int n = 0; n < Hdim; n++) s += Xs[n * MT + tid] * Hs[n];
            out[gm] = s;
        }
    }
}

extern "C" void kernel_launch(void* const* d_in, const int* in_sizes, int n_in,
                              void* d_out, int out_size) {
    const float* S    = (const float*)d_in[0];
    const float* T    = (const float*)d_in[1];
    const float* B    = (const float*)d_in[2];
    const float* in_w = (const float*)d_in[3];
    const float* in_b = (const float*)d_in[4];
    const float* w1   = (const float*)d_in[5];
    const float* b1   = (const float*)d_in[6];
    const float* w2   = (const float*)d_in[7];
    const float* b2   = (const float*)d_in[8];
    const float* skw  = (const float*)d_in[9];
    const float* skb  = (const float*)d_in[10];
    const float* ow   = (const float*)d_in[11];
    const float* ob   = (const float*)d_in[12];
    float* out        = (float*)d_out;

    int N = in_sizes[0];
    int grid = (N + MT - 1) / MT;
    size_t smem_bytes = SMEM_FLOATS * sizeof(float);

    cudaFuncSetAttribute(pinn_kernel, cudaFuncAttributeMaxDynamicSharedMemorySize,
                         (int)smem_bytes);
    pinn_kernel<<<grid, THREADS, smem_bytes>>>(S, T, B, in_w, in_b, w1, b1, w2, b2,
                                               skw, skb, ow, ob, out, N);
}

// round 4
// speedup vs baseline: 1.0030x; 1.0030x over previous
#include <cuda_runtime.h>
#include <math.h>

// FinancialPINN: Fourier-feature SIREN with residual blocks + periodic skips.
// Fully fused: one CTA processes a tile of 64 points through the entire
// network, keeping activations (transposed, [feature][point]) in shared
// memory and streaming each layer's weights into a shared 128x128 tile.
// Inner GEMM loops use packed fma.rn.f32x2 (FFMA2) for 2x fp32 throughput.

static constexpr int Fdim    = 128;   // Fourier features per trig fn
static constexpr int Hdim    = 128;   // hidden width
static constexpr int Ldim    = 8;     // residual blocks
static constexpr int MT      = 64;    // points per CTA
static constexpr int THREADS = 256;
static constexpr float OMEGA = 30.0f;

// shared layout (floats)
static constexpr int FF_OFF  = 0;                    // ff  [256][64]
static constexpr int XS_OFF  = FF_OFF + 2*Fdim*MT;   // Xs  [128][64]
static constexpr int HS_OFF  = XS_OFF + Hdim*MT;     // Hs  [128][64]
static constexpr int WS_OFF  = HS_OFF + Hdim*MT;     // Ws  [128][128]
static constexpr int SMEM_FLOATS = WS_OFF + Hdim*Hdim;  // 49152 floats = 192KB

typedef unsigned long long ull;

__device__ __forceinline__ ull pack2(float a) {
    ull r; asm("mov.b64 %0, {%1, %1};" : "=l"(r) : "f"(a)); return r;
}
__device__ __forceinline__ void unpack2(ull v, float& lo, float& hi) {
    asm("mov.b64 {%0, %1}, %2;" : "=f"(lo), "=f"(hi) : "l"(v));
}
__device__ __forceinline__ void fma2(ull& acc, ull x, ull w) {
    asm("fma.rn.f32x2 %0, %1, %2, %0;" : "+l"(acc) : "l"(x), "l"(w));
}

// Load a 128x128 f32 weight tile (contiguous in gmem) into Ws.
__device__ __forceinline__ void loadW(float* Ws, const float* __restrict__ g, int tid) {
    float4*       d = reinterpret_cast<float4*>(Ws);
    const float4* s = reinterpret_cast<const float4*>(g);
#pragma unroll
    for (int i = 0; i < 16; i++) d[tid + i * THREADS] = s[tid + i * THREADS];
}

// acc[mi][nj] (+)= A^T-tile @ W-tile.
// A: [K][MT] in smem (feature-major), W: [K][128] in smem.
// Thread (tx,ty): m = tx*4..tx*4+3, n = ty*8..ty*8+7 (as 4 packed pairs).
__device__ __forceinline__ void gemm_acc(const float* __restrict__ A,
                                         const float* __restrict__ W,
                                         int K, ull acc[4][4], int tx, int ty) {
    const float* a = A + tx * 4;
    const float* w = W + ty * 8;
#pragma unroll 8
    for (int k = 0; k < K; k++) {
        float4 xv = *reinterpret_cast<const float4*>(a);
        ulonglong2 w01 = *reinterpret_cast<const ulonglong2*>(w);
        ulonglong2 w23 = *reinterpret_cast<const ulonglong2*>(w + 4);
        a += MT;
        w += Hdim;
        ull xb0 = pack2(xv.x), xb1 = pack2(xv.y), xb2 = pack2(xv.z), xb3 = pack2(xv.w);
        ull wv0 = w01.x, wv1 = w01.y, wv2 = w23.x, wv3 = w23.y;
        fma2(acc[0][0], xb0, wv0); fma2(acc[0][1], xb0, wv1);
        fma2(acc[0][2], xb0, wv2); fma2(acc[0][3], xb0, wv3);
        fma2(acc[1][0], xb1, wv0); fma2(acc[1][1], xb1, wv1);
        fma2(acc[1][2], xb1, wv2); fma2(acc[1][3], xb1, wv3);
        fma2(acc[2][0], xb2, wv0); fma2(acc[2][1], xb2, wv1);
        fma2(acc[2][2], xb2, wv2); fma2(acc[2][3], xb2, wv3);
        fma2(acc[3][0], xb3, wv0); fma2(acc[3][1], xb3, wv1);
        fma2(acc[3][2], xb3, wv2); fma2(acc[3][3], xb3, wv3);
    }
}

__device__ __forceinline__ void zero_acc(ull acc[4][4]) {
#pragma unroll
    for (int i = 0; i < 4; i++)
#pragma unroll
        for (int j = 0; j < 4; j++) acc[i][j] = 0ULL;
}

extern __shared__ float smem[];

__global__ void __launch_bounds__(THREADS, 1)
pinn_kernel(const float* __restrict__ S,   const float* __restrict__ T,
            const float* __restrict__ B,
            const float* __restrict__ in_w, const float* __restrict__ in_b,
            const float* __restrict__ w1,   const float* __restrict__ b1,
            const float* __restrict__ w2,   const float* __restrict__ b2,
            const float* __restrict__ skw,  const float* __restrict__ skb,
            const float* __restrict__ ow,   const float* __restrict__ ob,
            float* __restrict__ out, int N) {
    float* ff = smem + FF_OFF;   // [2F][MT]
    float* Xs = smem + XS_OFF;   // [H][MT]
    float* Hs = smem + HS_OFF;   // [H][MT]
    float* Ws = smem + WS_OFF;   // [128][128]

    const int tid  = threadIdx.x;
    const int tx   = tid & 15;        // m direction
    const int ty   = tid >> 4;        // n direction
    const int mb   = tx * 4;
    const int nb   = ty * 8;
    const int base = blockIdx.x * MT;

    // ---- stage S,t for this tile into smem (reuse Hs as scratch) ----
    if (tid < MT) {
        int gm = base + tid;
        Hs[tid]      = (gm < N) ? S[gm] : 0.0f;
        Hs[MT + tid] = (gm < N) ? T[gm] : 0.0f;
    }
    __syncthreads();

    // ---- Fourier features: ff[f][m] = sin(proj), ff[F+f][m] = cos(proj) ----
#pragma unroll
    for (int i = 0; i < (2 * Fdim * MT / 2) / THREADS; i++) {   // 8192 (f,m) pairs / 256
        int e = tid + i * THREADS;
        int m = e & (MT - 1);
        int f = e >> 6;
        float proj = Hs[m] * B[f] + Hs[MT + m] * B[Fdim + f];
        float sn, cs;
        sincosf(proj, &sn, &cs);
        ff[f * MT + m]          = sn;
        ff[(f + Fdim) * MT + m] = cs;
    }
    __syncthreads();

    ull acc[4][4];

    // ---- input layer: x = sin(OMEGA * (ff @ in_w + in_b)), K = 256 ----
    zero_acc(acc);
    loadW(Ws, in_w, tid);
    __syncthreads();
    gemm_acc(ff, Ws, Fdim, acc, tx, ty);
    __syncthreads();
    loadW(Ws, in_w + Fdim * Hdim, tid);
    __syncthreads();
    gemm_acc(ff + Fdim * MT, Ws, Fdim, acc, tx, ty);
#pragma unroll
    for (int nj = 0; nj < 4; nj++) {
        float2 bb = *reinterpret_cast<const float2*>(in_b + nb + 2 * nj);
#pragma unroll
        for (int mi = 0; mi < 4; mi++) {
            float v0, v1; unpack2(acc[mi][nj], v0, v1);
            Xs[(nb + 2 * nj) * MT + mb + mi]     = sinf(OMEGA * (v0 + bb.x));
            Xs[(nb + 2 * nj + 1) * MT + mb + mi] = sinf(OMEGA * (v1 + bb.y));
        }
    }
    __syncthreads();

    // ---- residual blocks ----
    for (int layer = 0; layer < Ldim; layer++) {
        // h = tanh(x @ w1 + b1)
        loadW(Ws, w1 + layer * Hdim * Hdim, tid);
        __syncthreads();
        zero_acc(acc);
        gemm_acc(Xs, Ws, Hdim, acc, tx, ty);
#pragma unroll
        for (int nj = 0; nj < 4; nj++) {
            float2 bb = *reinterpret_cast<const float2*>(b1 + layer * Hdim + nb + 2 * nj);
#pragma unroll
            for (int mi = 0; mi < 4; mi++) {
                float v0, v1; unpack2(acc[mi][nj], v0, v1);
                Hs[(nb + 2 * nj) * MT + mb + mi]     = tanhf(v0 + bb.x);
                Hs[(nb + 2 * nj + 1) * MT + mb + mi] = tanhf(v1 + bb.y);
            }
        }
        __syncthreads();

        // acc = h @ w2   (b2 added at the end)
        loadW(Ws, w2 + layer * Hdim * Hdim, tid);
        __syncthreads();
        zero_acc(acc);
        gemm_acc(Hs, Ws, Hdim, acc, tx, ty);

        bool has_skip = ((layer & 1) == 0);
        if (has_skip) {
            // acc += ff @ skip_w[layer/2], K = 256 streamed as 2 chunks
            const float* sw = skw + (layer / 2) * (2 * Fdim) * Hdim;
            __syncthreads();               // gemm done reading Ws
            loadW(Ws, sw, tid);
            __syncthreads();
            gemm_acc(ff, Ws, Fdim, acc, tx, ty);
            __syncthreads();
            loadW(Ws, sw + Fdim * Hdim, tid);
            __syncthreads();
            gemm_acc(ff + Fdim * MT, Ws, Fdim, acc, tx, ty);
        }

        // x += acc + b2 (+ skip_b)
#pragma unroll
        for (int nj = 0; nj < 4; nj++) {
            float2 b2v = *reinterpret_cast<const float2*>(b2 + layer * Hdim + nb + 2 * nj);
            float2 sbv = make_float2(0.0f, 0.0f);
            if (has_skip)
                sbv = *reinterpret_cast<const float2*>(skb + (layer / 2) * Hdim + nb + 2 * nj);
#pragma unroll
            for (int mi = 0; mi < 4; mi++) {
                float v0, v1; unpack2(acc[mi][nj], v0, v1);
                Xs[(nb + 2 * nj) * MT + mb + mi]     += v0 + b2v.x + sbv.x;
                Xs[(nb + 2 * nj + 1) * MT + mb + mi] += v1 + b2v.y + sbv.y;
            }
        }
        __syncthreads();
    }

    // ---- output layer: out = x @ out_w + out_b ----
    if (tid < Hdim) Hs[tid] = ow[tid];     // Hs reused as out_w stage
    __syncthreads();
    if (tid < MT) {
        int gm = base + tid;
        if (gm < N) {
            float s = ob[0];
#pragma unroll 8
            for (int n = 0; n < Hdim; n++) s += Xs[n * MT + tid] * Hs[n];
            out[gm] = s;
        }
    }
}

extern "C" void kernel_launch(void* const* d_in, const int* in_sizes, int n_in,
                              void* d_out, int out_size) {
    const float* S    = (const float*)d_in[0];
    const float* T    = (const float*)d_in[1];
    const float* B    = (const float*)d_in[2];
    const float* in_w = (const float*)d_in[3];
    const float* in_b = (const float*)d_in[4];
    const float* w1   = (const float*)d_in[5];
    const float* b1   = (const float*)d_in[6];
    const float* w2   = (const float*)d_in[7];
    const float* b2   = (const float*)d_in[8];
    const float* skw  = (const float*)d_in[9];
    const float* skb  = (const float*)d_in[10];
    const float* ow   = (const float*)d_in[11];
    const float* ob   = (const float*)d_in[12];
    float* out        = (float*)d_out;

    int N = in_sizes[0];
    int grid = (N + MT - 1) / MT;
    size_t smem_bytes = SMEM_FLOATS * sizeof(float);

    cudaFuncSetAttribute(pinn_kernel, cudaFuncAttributeMaxDynamicSharedMemorySize,
                         (int)smem_bytes);
    pinn_kernel<<<grid, THREADS, smem_bytes>>>(S, T, B, in_w, in_b, w1, b1, w2, b2,
                                               skw, skb, ow, ob, out, N);
}

// round 6
// speedup vs baseline: 2.2007x; 2.1942x over previous
#include <cuda_runtime.h>
#include <cuda_bf16.h>
#include <stdint.h>
#include <math.h>

typedef uint32_t u32;
typedef uint64_t u64;

static constexpr int THREADS = 256;
static constexpr int MT      = 128;     // points per CTA
static constexpr float OMEGA = 30.0f;
static constexpr int NSUB    = 52;      // 26 units x (hi,lo) 32KB subunits
static constexpr int SUB_BYTES = 32768;

// ---- shared memory layout (bytes) ----
static constexpr int RING_OFF  = 0;            // 3 x 32KB weight ring
static constexpr int FFRAG_OFF = 98304;        // ff fragments: 8 warps x 16KB = 128KB
static constexpr int BOW_OFF   = 229376;       // B (256 f) + out_w (128 f)
static constexpr int MBAR_OFF  = 230912;       // 3 mbarriers
static constexpr int SMEM_BYTES = 231424;

// weight blob: 52 subunits x 32KB, execution order, bf16 [n][k] swizzled
__device__ __align__(16) unsigned char g_wblob[(size_t)NSUB * SUB_BYTES];

// ============================ PTX helpers ============================

__device__ __forceinline__ u32 smem_u32(const void* p) {
    return (u32)__cvta_generic_to_shared(p);
}

#define MBARRIER_INIT(addr, cnt) \
    asm volatile("mbarrier.init.shared.b64 [%0], %1;" :: "r"(addr), "r"((u32)(cnt)) : "memory")
#define MBARRIER_EXPECT_TX(addr, b) \
    asm volatile("mbarrier.arrive.expect_tx.shared.b64 _, [%0], %1;" :: "r"(addr), "r"((u32)(b)) : "memory")

#define MBARRIER_WAIT_PARITY(mbar_smem_addr, phase_parity) do { \
    u32 _mbar = (u32)(mbar_smem_addr); \
    u32 _parity = (u32)(phase_parity); \
    u32 _done; \
    asm volatile( \
        "{\n\t.reg .pred p;\n\t" \
        "mbarrier.try_wait.parity.acquire.cta.shared::cta.b64 p, [%1], %2;\n\t" \
        "selp.b32 %0, 1, 0, p;\n\t}" \
        : "=r"(_done) : "r"(_mbar), "r"(_parity) : "memory"); \
    if (!_done) { \
        asm volatile( \
            "{\n\t.reg .pred P1;\n\t" \
            "WAIT_LOOP_%=:\n\t" \
            "mbarrier.try_wait.parity.acquire.cta.shared::cta.b64 P1, [%0], %1, 0x989680;\n\t" \
            "@P1 bra.uni WAIT_DONE_%=;\n\t" \
            "bra.uni WAIT_LOOP_%=;\n\t" \
            "WAIT_DONE_%=:\n\t}" \
            :: "r"(_mbar), "r"(_parity) : "memory"); \
    } \
} while (0)

__device__ __forceinline__ void bulk_copy(u32 dst, const void* src, u32 bytes, u32 mbar) {
    asm volatile(
        "cp.async.bulk.shared::cluster.global.mbarrier::complete_tx::bytes [%0], [%1], %2, [%3];"
        :: "r"(dst), "l"(src), "r"(bytes), "r"(mbar) : "memory");
}

__device__ __forceinline__ void ldsm4(u32& r0, u32& r1, u32& r2, u32& r3, u32 addr) {
    asm volatile("ldmatrix.sync.aligned.m8n8.x4.shared.b16 {%0,%1,%2,%3}, [%4];"
                 : "=r"(r0), "=r"(r1), "=r"(r2), "=r"(r3) : "r"(addr));
}

__device__ __forceinline__ void mma16816(float (&d)[4], const u32 (&a)[4], u32 b0, u32 b1) {
    asm volatile(
        "mma.sync.aligned.m16n8k16.row.col.f32.bf16.bf16.f32 "
        "{%0,%1,%2,%3},{%4,%5,%6,%7},{%8,%9},{%0,%1,%2,%3};"
        : "+f"(d[0]), "+f"(d[1]), "+f"(d[2]), "+f"(d[3])
        : "r"(a[0]), "r"(a[1]), "r"(a[2]), "r"(a[3]), "r"(b0), "r"(b1));
}

__device__ __forceinline__ void bf_split2(float v0, float v1, u32& hi, u32& lo) {
    __nv_bfloat16 h0 = __float2bfloat16_rn(v0), h1 = __float2bfloat16_rn(v1);
    float r0 = v0 - __bfloat162float(h0);
    float r1 = v1 - __bfloat162float(h1);
    __nv_bfloat16 l0 = __float2bfloat16_rn(r0), l1 = __float2bfloat16_rn(r1);
    hi = (u32)__bfloat16_as_ushort(h0) | ((u32)__bfloat16_as_ushort(h1) << 16);
    lo = (u32)__bfloat16_as_ushort(l0) | ((u32)__bfloat16_as_ushort(l1) << 16);
}
__device__ __forceinline__ float bflo(u32 v) {
    return __bfloat162float(__ushort_as_bfloat16((unsigned short)(v & 0xFFFF)));
}
__device__ __forceinline__ float bfhi(u32 v) {
    return __bfloat162float(__ushort_as_bfloat16((unsigned short)(v >> 16)));
}

// ==================== weight conversion pre-kernel ====================
// Unit order: in_w k0-127, in_w k128-255, then per layer l: w1_l, w2_l,
// (+ skw[l/2] k-chunk0, chunk1 when l even). Element (n,k) = W[k][n].
// In-tile layout: row n = 256B (128 bf16 of k), byte = n*256 + (2k ^ ((n&7)<<4)).
__global__ void convert_weights(const float* __restrict__ in_w,
                                const float* __restrict__ w1,
                                const float* __restrict__ w2,
                                const float* __restrict__ skw) {
    int gid = blockIdx.x * blockDim.x + threadIdx.x;
    if (gid >= 26 * 16384) return;
    int u = gid >> 14, e = gid & 16383;
    int n = e >> 7, k = e & 127;

    float v;
    if (u < 2) {
        v = in_w[(k + u * 128) * 128 + n];
    } else {
        int r = u - 2, l = 0;
        while (true) {
            int len = ((l & 1) == 0) ? 4 : 2;
            if (r < len) break;
            r -= len; l++;
        }
        if (r == 0)      v = w1[l * 16384 + k * 128 + n];
        else if (r == 1) v = w2[l * 16384 + k * 128 + n];
        else             v = skw[(l >> 1) * 32768 + (k + (r - 2) * 128) * 128 + n];
    }

    __nv_bfloat16 hi = __float2bfloat16_rn(v);
    float rem = v - __bfloat162float(hi);
    __nv_bfloat16 lo = __float2bfloat16_rn(rem);

    u32 off = (u32)(n * 256 + ((2 * k) ^ ((n & 7) << 4)));
    size_t base = (size_t)u * 65536;
    *(__nv_bfloat16*)(g_wblob + base + off)         = hi;
    *(__nv_bfloat16*)(g_wblob + base + 32768 + off) = lo;
}

// ==================== GEMM subunit helpers ====================
// Warp tile: m16 x n128 (16 ntiles). A row-major m16k16 frags, B = Wt[n][k]
// (col-major K x N), loaded via ldmatrix.x4 (2 ntiles x 1 kstep per ldsm).

__device__ __forceinline__ void gemm_x(u32 wbase, const u32 (&ah)[8][4], const u32 (&al)[8][4],
                                       bool isHi, float (&d)[16][4], int lane) {
    const u32 off0 = (u32)((((lane & 7) + ((lane >> 4) << 3))) * 256);
    const u32 swz  = (u32)((lane & 7) << 4);
    const u32 kh   = (u32)(((lane >> 3) & 1) * 16);
#pragma unroll
    for (int s = 0; s < 8; s++) {
#pragma unroll
        for (int ntp = 0; ntp < 8; ntp++) {
            u32 r0, r1, r2, r3;
            ldsm4(r0, r1, r2, r3, wbase + off0 + (u32)(ntp * 4096) + (((u32)(32 * s) + kh) ^ swz));
            mma16816(d[2 * ntp],     ah[s], r0, r1);
            mma16816(d[2 * ntp + 1], ah[s], r2, r3);
            if (isHi) {
                mma16816(d[2 * ntp],     al[s], r0, r1);
                mma16816(d[2 * ntp + 1], al[s], r2, r3);
            }
        }
    }
}

__device__ __forceinline__ void gemm_ff(u32 wbase, const char* fr, int kbase,
                                        bool isHi, float (&d)[16][4], int lane) {
    const u32 off0 = (u32)((((lane & 7) + ((lane >> 4) << 3))) * 256);
    const u32 swz  = (u32)((lane & 7) << 4);
    const u32 kh   = (u32)(((lane >> 3) & 1) * 16);
#pragma unroll
    for (int s = 0; s < 8; s++) {
        const int4 q0 = *(const int4*)(fr + ((kbase + s) * 2 + 0) * 512);
        const int4 q1 = *(const int4*)(fr + ((kbase + s) * 2 + 1) * 512);
        u32 ah[4] = {(u32)q0.x, (u32)q1.x, (u32)q0.y, (u32)q1.y};
        u32 al[4] = {(u32)q0.z, (u32)q1.z, (u32)q0.w, (u32)q1.w};
#pragma unroll
        for (int ntp = 0; ntp < 8; ntp++) {
            u32 r0, r1, r2, r3;
            ldsm4(r0, r1, r2, r3, wbase + off0 + (u32)(ntp * 4096) + (((u32)(32 * s) + kh) ^ swz));
            mma16816(d[2 * ntp],     ah, r0, r1);
            mma16816(d[2 * ntp + 1], ah, r2, r3);
            if (isHi) {
                mma16816(d[2 * ntp],     al, r0, r1);
                mma16816(d[2 * ntp + 1], al, r2, r3);
            }
        }
    }
}

__device__ __forceinline__ void zero_d(float (&d)[16][4]) {
#pragma unroll
    for (int i = 0; i < 16; i++)
#pragma unroll
        for (int j = 0; j < 4; j++) d[i][j] = 0.0f;
}

__device__ __forceinline__ void gate_wait(u32 mbf, int sub) {
    MBARRIER_WAIT_PARITY(mbf + 8 * (sub % 3), (sub / 3) & 1);
}
__device__ __forceinline__ void prefetch_sub(u32 ring, u32 mbf, int sub) {
    u32 mb = mbf + 8 * (sub % 3);
    MBARRIER_EXPECT_TX(mb, SUB_BYTES);
    bulk_copy(ring + (sub % 3) * SUB_BYTES, g_wblob + (size_t)sub * SUB_BYTES, SUB_BYTES, mb);
}

// ==================== main kernel ====================

extern __shared__ __align__(16) char smem[];

__global__ void __launch_bounds__(THREADS, 1)
pinn_mma(const float* __restrict__ S,  const float* __restrict__ Tt,
         const float* __restrict__ Bm,
         const float* __restrict__ in_b, const float* __restrict__ b1,
         const float* __restrict__ b2,   const float* __restrict__ skb,
         const float* __restrict__ ow,   const float* __restrict__ ob,
         float* __restrict__ out, int N)
{
    const int tid  = threadIdx.x;
    const int warp = tid >> 5, lane = tid & 31;
    const int grp  = lane >> 2, qc = lane & 3;
    const int base = blockIdx.x * MT;

    const u32 sb   = smem_u32(smem);
    const u32 ring = sb + RING_OFF;
    const u32 mbf  = sb + MBAR_OFF;
    float* Bs  = (float*)(smem + BOW_OFF);      // 256 floats
    float* ows = Bs + 256;                      // 128 floats
    char*  fr  = smem + FFRAG_OFF + warp * 16384 + lane * 16;  // this thread's frag base

    if (tid == 0) {
        MBARRIER_INIT(mbf + 0,  1);
        MBARRIER_INIT(mbf + 8,  1);
        MBARRIER_INIT(mbf + 16, 1);
    }
    __syncthreads();   // barrier init visible before any wait/expect ordering below

    if (tid == 0) {
        prefetch_sub(ring, mbf, 0);
        prefetch_sub(ring, mbf, 1);
        prefetch_sub(ring, mbf, 2);
    }

    // stage B and out_w
    if (tid < 256) Bs[tid] = Bm[tid];
    if (tid < 128) ows[tid] = ow[tid];

    // this thread's two point rows
    const int r0g = base + warp * 16 + grp;
    const int r1g = r0g + 8;
    const float s0 = (r0g < N) ? S[r0g]  : 0.0f;
    const float t0 = (r0g < N) ? Tt[r0g] : 0.0f;
    const float s1 = (r1g < N) ? S[r1g]  : 0.0f;
    const float t1 = (r1g < N) ? Tt[r1g] : 0.0f;
    __syncthreads();

    // ---- Fourier-feature A fragments -> per-warp smem (overlaps weight copies) ----
    // A[m][k]: k<128 sin(proj[f=k]); k>=128 cos(proj[f=k-128]).
    // kstep t (sin) / t+8 (cos); within kstep, this thread needs f = 16t + {2qc,2qc+1,2qc+8,2qc+9}.
#pragma unroll
    for (int t = 0; t < 8; t++) {
        int f0 = 16 * t + 2 * qc;
        float sn[2][4], cs[2][4];
#pragma unroll
        for (int j = 0; j < 4; j++) {
            int f = f0 + ((j & 1) ? 1 : 0) + ((j & 2) ? 8 : 0);
            float p0 = s0 * Bs[f] + t0 * Bs[128 + f];
            float p1 = s1 * Bs[f] + t1 * Bs[128 + f];
            sincosf(p0, &sn[0][j], &cs[0][j]);
            sincosf(p1, &sn[1][j], &cs[1][j]);
        }
        u32 h0, l0, h1, l1, h2, l2, h3, l3;
        // sin -> kstep t
        bf_split2(sn[0][0], sn[0][1], h0, l0);   // a0: row grp,  f0,f0+1
        bf_split2(sn[1][0], sn[1][1], h1, l1);   // a1: row grp+8
        bf_split2(sn[0][2], sn[0][3], h2, l2);   // a2: row grp,  f0+8,f0+9
        bf_split2(sn[1][2], sn[1][3], h3, l3);   // a3
        *(int4*)(fr + (t * 2 + 0) * 512) = make_int4((int)h0, (int)h2, (int)l0, (int)l2);
        *(int4*)(fr + (t * 2 + 1) * 512) = make_int4((int)h1, (int)h3, (int)l1, (int)l3);
        // cos -> kstep t+8
        bf_split2(cs[0][0], cs[0][1], h0, l0);
        bf_split2(cs[1][0], cs[1][1], h1, l1);
        bf_split2(cs[0][2], cs[0][3], h2, l2);
        bf_split2(cs[1][2], cs[1][3], h3, l3);
        *(int4*)(fr + ((t + 8) * 2 + 0) * 512) = make_int4((int)h0, (int)h2, (int)l0, (int)l2);
        *(int4*)(fr + ((t + 8) * 2 + 1) * 512) = make_int4((int)h1, (int)h3, (int)l1, (int)l3);
    }
    // (no sync needed: each thread reads back only its own records)

    int sub = 0;
    float d[16][4];
    u32 xh[8][4], xl[8][4];

#define DO_FF(kbase, isHi) do { \
        gate_wait(mbf, sub); \
        gemm_ff(ring + (u32)((sub % 3) * SUB_BYTES), fr, (kbase), (isHi), d, lane); \
        __syncthreads(); \
        if (tid == 0 && sub + 3 < NSUB) prefetch_sub(ring, mbf, sub + 3); \
        sub++; \
    } while (0)

#define DO_X(AH, AL, isHi) do { \
        gate_wait(mbf, sub); \
        gemm_x(ring + (u32)((sub % 3) * SUB_BYTES), (AH), (AL), (isHi), d, lane); \
        __syncthreads(); \
        if (tid == 0 && sub + 3 < NSUB) prefetch_sub(ring, mbf, sub + 3); \
        sub++; \
    } while (0)

    // ---- input layer: D = ff @ in_w (K=256), x = sin(OMEGA*(D + in_b)) ----
    zero_d(d);
    DO_FF(0, true);  DO_FF(0, false);
    DO_FF(8, true);  DO_FF(8, false);

#pragma unroll
    for (int s = 0; s < 8; s++) {
#pragma unroll
        for (int p = 0; p < 2; p++) {
            int nt = 2 * s + p;
            int col = 8 * nt + 2 * qc;
            float2 bb = *(const float2*)(in_b + col);
            float v00 = sinf(OMEGA * (d[nt][0] + bb.x));
            float v01 = sinf(OMEGA * (d[nt][1] + bb.y));
            float v10 = sinf(OMEGA * (d[nt][2] + bb.x));
            float v11 = sinf(OMEGA * (d[nt][3] + bb.y));
            bf_split2(v00, v01, xh[s][2 * p],     xl[s][2 * p]);
            bf_split2(v10, v11, xh[s][2 * p + 1], xl[s][2 * p + 1]);
        }
    }

    // ---- residual blocks ----
    for (int l = 0; l < 8; l++) {
        const bool skip = ((l & 1) == 0);
        u32 hh[8][4], hl[8][4];

        // GEMM1: D = x @ w1_l ; h = tanh(D + b1_l)
        zero_d(d);
        DO_X(xh, xl, true);  DO_X(xh, xl, false);
#pragma unroll
        for (int s = 0; s < 8; s++) {
#pragma unroll
            for (int p = 0; p < 2; p++) {
                int nt = 2 * s + p;
                int col = 8 * nt + 2 * qc;
                float2 bb = *(const float2*)(b1 + l * 128 + col);
                float v00 = tanhf(d[nt][0] + bb.x);
                float v01 = tanhf(d[nt][1] + bb.y);
                float v10 = tanhf(d[nt][2] + bb.x);
                float v11 = tanhf(d[nt][3] + bb.y);
                bf_split2(v00, v01, hh[s][2 * p],     hl[s][2 * p]);
                bf_split2(v10, v11, hh[s][2 * p + 1], hl[s][2 * p + 1]);
            }
        }

        // GEMM2: D = h @ w2_l (+ ff @ skip_w[l/2])
        zero_d(d);
        DO_X(hh, hl, true);  DO_X(hh, hl, false);
        if (skip) {
            DO_FF(0, true);  DO_FF(0, false);
            DO_FF(8, true);  DO_FF(8, false);
        }

        // epilogue2: x = x + D + b2 (+ skb); re-split into frags
#pragma unroll
        for (int s = 0; s < 8; s++) {
#pragma unroll
            for (int p = 0; p < 2; p++) {
                int nt = 2 * s + p;
                int col = 8 * nt + 2 * qc;
                float2 bb = *(const float2*)(b2 + l * 128 + col);
                float sbx = 0.0f, sby = 0.0f;
                if (skip) {
                    float2 sv = *(const float2*)(skb + (l >> 1) * 128 + col);
                    sbx = sv.x; sby = sv.y;
                }
                int i0 = 2 * p, i1 = 2 * p + 1;
                float v00 = bflo(xh[s][i0]) + bflo(xl[s][i0]) + d[nt][0] + bb.x + sbx;
                float v01 = bfhi(xh[s][i0]) + bfhi(xl[s][i0]) + d[nt][1] + bb.y + sby;
                float v10 = bflo(xh[s][i1]) + bflo(xl[s][i1]) + d[nt][2] + bb.x + sbx;
                float v11 = bfhi(xh[s][i1]) + bfhi(xl[s][i1]) + d[nt][3] + bb.y + sby;
                bf_split2(v00, v01, xh[s][i0], xl[s][i0]);
                bf_split2(v10, v11, xh[s][i1], xl[s][i1]);
            }
        }
    }

    // ---- output layer: out = x @ out_w + out_b ----
    float a0 = 0.0f, a1 = 0.0f;
#pragma unroll
    for (int s = 0; s < 8; s++) {
#pragma unroll
        for (int p = 0; p < 2; p++) {
            int nt = 2 * s + p;
            int col = 8 * nt + 2 * qc;
            float w0 = ows[col], w1v = ows[col + 1];
            int i0 = 2 * p, i1 = 2 * p + 1;
            a0 += (bflo(xh[s][i0]) + bflo(xl[s][i0])) * w0
                + (bfhi(xh[s][i0]) + bfhi(xl[s][i0])) * w1v;
            a1 += (bflo(xh[s][i1]) + bflo(xl[s][i1])) * w0
                + (bfhi(xh[s][i1]) + bfhi(xl[s][i1])) * w1v;
        }
    }
    a0 += __shfl_xor_sync(0xFFFFFFFF, a0, 1);
    a0 += __shfl_xor_sync(0xFFFFFFFF, a0, 2);
    a1 += __shfl_xor_sync(0xFFFFFFFF, a1, 1);
    a1 += __shfl_xor_sync(0xFFFFFFFF, a1, 2);
    if (qc == 0) {
        float obv = ob[0];
        if (r0g < N) out[r0g] = a0 + obv;
        if (r1g < N) out[r1g] = a1 + obv;
    }
#undef DO_FF
#undef DO_X
}

// ==================== launcher ====================

extern "C" void kernel_launch(void* const* d_in, const int* in_sizes, int n_in,
                              void* d_out, int out_size) {
    const float* S    = (const float*)d_in[0];
    const float* T    = (const float*)d_in[1];
    const float* B    = (const float*)d_in[2];
    const float* in_w = (const float*)d_in[3];
    const float* in_b = (const float*)d_in[4];
    const float* w1   = (const float*)d_in[5];
    const float* b1   = (const float*)d_in[6];
    const float* w2   = (const float*)d_in[7];
    const float* b2   = (const float*)d_in[8];
    const float* skw  = (const float*)d_in[9];
    const float* skb  = (const float*)d_in[10];
    const float* ow   = (const float*)d_in[11];
    const float* ob   = (const float*)d_in[12];
    float* out        = (float*)d_out;

    int N = in_sizes[0];

    convert_weights<<<(26 * 16384 + 255) / 256, 256>>>(in_w, w1, w2, skw);

    cudaFuncSetAttribute(pinn_mma, cudaFuncAttributeMaxDynamicSharedMemorySize, SMEM_BYTES);
    int grid = (N + MT - 1) / MT;
    pinn_mma<<<grid, THREADS, SMEM_BYTES>>>(S, T, B, in_b, b1, b2, skb, ow, ob, out, N);
}

// round 7
// speedup vs baseline: 2.3578x; 1.0714x over previous
#include <cuda_runtime.h>
#include <cuda_bf16.h>
#include <stdint.h>
#include <math.h>

typedef uint32_t u32;
typedef uint64_t u64;

static constexpr int THREADS = 256;
static constexpr int MT      = 128;     // points per CTA
static constexpr float OMEGA = 30.0f;
static constexpr int NSUB    = 52;      // 26 units x (hi,lo) 32KB subunits
static constexpr int SUB_BYTES = 32768;

// ---- shared memory layout (bytes) ----
static constexpr int RING_OFF  = 0;            // 3 x 32KB weight ring
static constexpr int FFRAG_OFF = 98304;        // ff fragments: 8 warps x 16KB = 128KB
static constexpr int BOW_OFF   = 229376;       // B (256 f) + out_w (128 f)
static constexpr int MBAR_OFF  = 230912;       // full[3] + empty[3]
static constexpr int SMEM_BYTES = 231424;

// weight blob: 52 subunits x 32KB, execution order, bf16 [n][k] swizzled
__device__ __align__(16) unsigned char g_wblob[(size_t)NSUB * SUB_BYTES];

// ============================ PTX helpers ============================

__device__ __forceinline__ u32 smem_u32(const void* p) {
    return (u32)__cvta_generic_to_shared(p);
}

#define MBARRIER_INIT(addr, cnt) \
    asm volatile("mbarrier.init.shared.b64 [%0], %1;" :: "r"(addr), "r"((u32)(cnt)) : "memory")
#define MBARRIER_EXPECT_TX(addr, b) \
    asm volatile("mbarrier.arrive.expect_tx.shared.b64 _, [%0], %1;" :: "r"(addr), "r"((u32)(b)) : "memory")
#define MBARRIER_ARRIVE(addr) \
    asm volatile("mbarrier.arrive.shared.b64 _, [%0];" :: "r"(addr) : "memory")

#define MBARRIER_WAIT_PARITY(mbar_smem_addr, phase_parity) do { \
    u32 _mbar = (u32)(mbar_smem_addr); \
    u32 _parity = (u32)(phase_parity); \
    u32 _done; \
    asm volatile( \
        "{\n\t.reg .pred p;\n\t" \
        "mbarrier.try_wait.parity.acquire.cta.shared::cta.b64 p, [%1], %2;\n\t" \
        "selp.b32 %0, 1, 0, p;\n\t}" \
        : "=r"(_done) : "r"(_mbar), "r"(_parity) : "memory"); \
    if (!_done) { \
        asm volatile( \
            "{\n\t.reg .pred P1;\n\t" \
            "WAIT_LOOP_%=:\n\t" \
            "mbarrier.try_wait.parity.acquire.cta.shared::cta.b64 P1, [%0], %1, 0x989680;\n\t" \
            "@P1 bra.uni WAIT_DONE_%=;\n\t" \
            "bra.uni WAIT_LOOP_%=;\n\t" \
            "WAIT_DONE_%=:\n\t}" \
            :: "r"(_mbar), "r"(_parity) : "memory"); \
    } \
} while (0)

// Relaxed wait: post-wait SMEM access is async-proxy only (cp.async.bulk).
#define MBARRIER_WAIT_PARITY_RELAXED(mbar_smem_addr, phase_parity) do { \
    u32 _mbar = (u32)(mbar_smem_addr); \
    u32 _parity = (u32)(phase_parity); \
    u32 _done; \
    asm volatile( \
        "{\n\t.reg .pred p;\n\t" \
        "mbarrier.try_wait.parity.relaxed.cta.shared::cta.b64 p, [%1], %2, 0x989680;\n\t" \
        "selp.b32 %0, 1, 0, p;\n\t}" \
        : "=r"(_done) : "r"(_mbar), "r"(_parity) : "memory"); \
    if (!_done) { \
        asm volatile( \
            "{\n\t.reg .pred P1;\n\t" \
            "WAIT_LOOP_%=:\n\t" \
            "mbarrier.try_wait.parity.relaxed.cta.shared::cta.b64 P1, [%0], %1, 0x989680;\n\t" \
            "@P1 bra.uni WAIT_DONE_%=;\n\t" \
            "bra.uni WAIT_LOOP_%=;\n\t" \
            "WAIT_DONE_%=:\n\t}" \
            :: "r"(_mbar), "r"(_parity) : "memory"); \
    } \
} while (0)

__device__ __forceinline__ void bulk_copy(u32 dst, const void* src, u32 bytes, u32 mbar) {
    asm volatile(
        "cp.async.bulk.shared::cluster.global.mbarrier::complete_tx::bytes [%0], [%1], %2, [%3];"
        :: "r"(dst), "l"(src), "r"(bytes), "r"(mbar) : "memory");
}

__device__ __forceinline__ void ldsm4(u32& r0, u32& r1, u32& r2, u32& r3, u32 addr) {
    asm volatile("ldmatrix.sync.aligned.m8n8.x4.shared.b16 {%0,%1,%2,%3}, [%4];"
                 : "=r"(r0), "=r"(r1), "=r"(r2), "=r"(r3) : "r"(addr));
}

__device__ __forceinline__ void mma16816(float (&d)[4], const u32 (&a)[4], u32 b0, u32 b1) {
    asm volatile(
        "mma.sync.aligned.m16n8k16.row.col.f32.bf16.bf16.f32 "
        "{%0,%1,%2,%3},{%4,%5,%6,%7},{%8,%9},{%0,%1,%2,%3};"
        : "+f"(d[0]), "+f"(d[1]), "+f"(d[2]), "+f"(d[3])
        : "r"(a[0]), "r"(a[1]), "r"(a[2]), "r"(a[3]), "r"(b0), "r"(b1));
}

__device__ __forceinline__ void bf_split2(float v0, float v1, u32& hi, u32& lo) {
    __nv_bfloat16 h0 = __float2bfloat16_rn(v0), h1 = __float2bfloat16_rn(v1);
    float r0 = v0 - __bfloat162float(h0);
    float r1 = v1 - __bfloat162float(h1);
    __nv_bfloat16 l0 = __float2bfloat16_rn(r0), l1 = __float2bfloat16_rn(r1);
    hi = (u32)__bfloat16_as_ushort(h0) | ((u32)__bfloat16_as_ushort(h1) << 16);
    lo = (u32)__bfloat16_as_ushort(l0) | ((u32)__bfloat16_as_ushort(l1) << 16);
}
__device__ __forceinline__ float bflo(u32 v) {
    return __bfloat162float(__ushort_as_bfloat16((unsigned short)(v & 0xFFFF)));
}
__device__ __forceinline__ float bfhi(u32 v) {
    return __bfloat162float(__ushort_as_bfloat16((unsigned short)(v >> 16)));
}

// ==================== weight conversion pre-kernel ====================
// Unit order: in_w k0-127, in_w k128-255, then per layer l: w1_l, w2_l,
// (+ skw[l/2] k-chunk0, chunk1 when l even). Element (n,k) = W[k][n].
// In-tile layout: row n = 256B (128 bf16 of k), byte = n*256 + (2k ^ ((n&7)<<4)).
__global__ void convert_weights(const float* __restrict__ in_w,
                                const float* __restrict__ w1,
                                const float* __restrict__ w2,
                                const float* __restrict__ skw) {
    int gid = blockIdx.x * blockDim.x + threadIdx.x;
    if (gid >= 26 * 16384) return;
    int u = gid >> 14, e = gid & 16383;
    int n = e >> 7, k = e & 127;

    float v;
    if (u < 2) {
        v = in_w[(k + u * 128) * 128 + n];
    } else {
        int r = u - 2, l = 0;
        while (true) {
            int len = ((l & 1) == 0) ? 4 : 2;
            if (r < len) break;
            r -= len; l++;
        }
        if (r == 0)      v = w1[l * 16384 + k * 128 + n];
        else if (r == 1) v = w2[l * 16384 + k * 128 + n];
        else             v = skw[(l >> 1) * 32768 + (k + (r - 2) * 128) * 128 + n];
    }

    __nv_bfloat16 hi = __float2bfloat16_rn(v);
    float rem = v - __bfloat162float(hi);
    __nv_bfloat16 lo = __float2bfloat16_rn(rem);

    u32 off = (u32)(n * 256 + ((2 * k) ^ ((n & 7) << 4)));
    size_t base = (size_t)u * 65536;
    *(__nv_bfloat16*)(g_wblob + base + off)         = hi;
    *(__nv_bfloat16*)(g_wblob + base + 32768 + off) = lo;
}

// ==================== GEMM subunit helpers ====================
// Warp tile: m16 x n128 (16 ntiles). A row-major m16k16 frags, B = Wt[n][k]
// (col-major K x N), loaded via ldmatrix.x4 (2 ntiles x 1 kstep per ldsm).

__device__ __forceinline__ void gemm_x(u32 wbase, const u32 (&ah)[8][4], const u32 (&al)[8][4],
                                       bool isHi, float (&d)[16][4], int lane) {
    const u32 off0 = (u32)((((lane & 7) + ((lane >> 4) << 3))) * 256);
    const u32 swz  = (u32)((lane & 7) << 4);
    const u32 kh   = (u32)(((lane >> 3) & 1) * 16);
#pragma unroll
    for (int s = 0; s < 8; s++) {
#pragma unroll
        for (int ntp = 0; ntp < 8; ntp++) {
            u32 r0, r1, r2, r3;
            ldsm4(r0, r1, r2, r3, wbase + off0 + (u32)(ntp * 4096) + (((u32)(32 * s) + kh) ^ swz));
            mma16816(d[2 * ntp],     ah[s], r0, r1);
            mma16816(d[2 * ntp + 1], ah[s], r2, r3);
            if (isHi) {
                mma16816(d[2 * ntp],     al[s], r0, r1);
                mma16816(d[2 * ntp + 1], al[s], r2, r3);
            }
        }
    }
}

__device__ __forceinline__ void gemm_ff(u32 wbase, const char* fr, int kbase,
                                        bool isHi, float (&d)[16][4], int lane) {
    const u32 off0 = (u32)((((lane & 7) + ((lane >> 4) << 3))) * 256);
    const u32 swz  = (u32)((lane & 7) << 4);
    const u32 kh   = (u32)(((lane >> 3) & 1) * 16);
#pragma unroll
    for (int s = 0; s < 8; s++) {
        const int4 q0 = *(const int4*)(fr + ((kbase + s) * 2 + 0) * 512);
        const int4 q1 = *(const int4*)(fr + ((kbase + s) * 2 + 1) * 512);
        u32 ah[4] = {(u32)q0.x, (u32)q1.x, (u32)q0.y, (u32)q1.y};
        u32 al[4] = {(u32)q0.z, (u32)q1.z, (u32)q0.w, (u32)q1.w};
#pragma unroll
        for (int ntp = 0; ntp < 8; ntp++) {
            u32 r0, r1, r2, r3;
            ldsm4(r0, r1, r2, r3, wbase + off0 + (u32)(ntp * 4096) + (((u32)(32 * s) + kh) ^ swz));
            mma16816(d[2 * ntp],     ah, r0, r1);
            mma16816(d[2 * ntp + 1], ah, r2, r3);
            if (isHi) {
                mma16816(d[2 * ntp],     al, r0, r1);
                mma16816(d[2 * ntp + 1], al, r2, r3);
            }
        }
    }
}

__device__ __forceinline__ void zero_d(float (&d)[16][4]) {
#pragma unroll
    for (int i = 0; i < 16; i++)
#pragma unroll
        for (int j = 0; j < 4; j++) d[i][j] = 0.0f;
}

__device__ __forceinline__ void prefetch_sub(u32 ring, u32 mbf, int sub) {
    u32 mb = mbf + 8 * (sub % 3);
    MBARRIER_EXPECT_TX(mb, SUB_BYTES);
    bulk_copy(ring + (sub % 3) * SUB_BYTES, g_wblob + (size_t)sub * SUB_BYTES, SUB_BYTES, mb);
}

// ==================== main kernel ====================

extern __shared__ __align__(16) char smem[];

__global__ void __launch_bounds__(THREADS, 1)
pinn_mma(const float* __restrict__ S,  const float* __restrict__ Tt,
         const float* __restrict__ Bm,
         const float* __restrict__ in_b, const float* __restrict__ b1,
         const float* __restrict__ b2,   const float* __restrict__ skb,
         const float* __restrict__ ow,   const float* __restrict__ ob,
         float* __restrict__ out, int N)
{
    const int tid  = threadIdx.x;
    const int warp = tid >> 5, lane = tid & 31;
    const int grp  = lane >> 2, qc = lane & 3;
    const int base = blockIdx.x * MT;

    const u32 sb   = smem_u32(smem);
    const u32 ring = sb + RING_OFF;
    const u32 mbf  = sb + MBAR_OFF;        // full[3] at +0,8,16
    const u32 mbe  = sb + MBAR_OFF + 24;   // empty[3] at +24,32,40
    float* Bs  = (float*)(smem + BOW_OFF);      // 256 floats
    float* ows = Bs + 256;                      // 128 floats
    char*  fr  = smem + FFRAG_OFF + warp * 16384 + lane * 16;  // this thread's frag base

    if (tid == 0) {
        MBARRIER_INIT(mbf + 0,  1);
        MBARRIER_INIT(mbf + 8,  1);
        MBARRIER_INIT(mbf + 16, 1);
        MBARRIER_INIT(mbe + 0,  8);
        MBARRIER_INIT(mbe + 8,  8);
        MBARRIER_INIT(mbe + 16, 8);
    }
    __syncthreads();   // barrier init visible before any wait/expect/arrive below

    if (tid == 0) {
        prefetch_sub(ring, mbf, 0);
        prefetch_sub(ring, mbf, 1);
        prefetch_sub(ring, mbf, 2);
    }

    // stage B and out_w
    if (tid < 256) Bs[tid] = Bm[tid];
    if (tid < 128) ows[tid] = ow[tid];

    // this thread's two point rows
    const int r0g = base + warp * 16 + grp;
    const int r1g = r0g + 8;
    const float s0 = (r0g < N) ? S[r0g]  : 0.0f;
    const float t0 = (r0g < N) ? Tt[r0g] : 0.0f;
    const float s1 = (r1g < N) ? S[r1g]  : 0.0f;
    const float t1 = (r1g < N) ? Tt[r1g] : 0.0f;
    __syncthreads();

    // ---- Fourier-feature A fragments -> per-warp smem (overlaps weight copies) ----
    // A[m][k]: k<128 sin(proj[f=k]); k>=128 cos(proj[f=k-128]).
    // kstep t (sin) / t+8 (cos); within kstep, this thread needs f = 16t + {2qc,2qc+1,2qc+8,2qc+9}.
#pragma unroll
    for (int t = 0; t < 8; t++) {
        int f0 = 16 * t + 2 * qc;
        float sn[2][4], cs[2][4];
#pragma unroll
        for (int j = 0; j < 4; j++) {
            int f = f0 + ((j & 1) ? 1 : 0) + ((j & 2) ? 8 : 0);
            float p0 = s0 * Bs[f] + t0 * Bs[128 + f];
            float p1 = s1 * Bs[f] + t1 * Bs[128 + f];
            sincosf(p0, &sn[0][j], &cs[0][j]);
            sincosf(p1, &sn[1][j], &cs[1][j]);
        }
        u32 h0, l0, h1, l1, h2, l2, h3, l3;
        // sin -> kstep t
        bf_split2(sn[0][0], sn[0][1], h0, l0);   // a0: row grp,  f0,f0+1
        bf_split2(sn[1][0], sn[1][1], h1, l1);   // a1: row grp+8
        bf_split2(sn[0][2], sn[0][3], h2, l2);   // a2: row grp,  f0+8,f0+9
        bf_split2(sn[1][2], sn[1][3], h3, l3);   // a3
        *(int4*)(fr + (t * 2 + 0) * 512) = make_int4((int)h0, (int)h2, (int)l0, (int)l2);
        *(int4*)(fr + (t * 2 + 1) * 512) = make_int4((int)h1, (int)h3, (int)l1, (int)l3);
        // cos -> kstep t+8
        bf_split2(cs[0][0], cs[0][1], h0, l0);
        bf_split2(cs[1][0], cs[1][1], h1, l1);
        bf_split2(cs[0][2], cs[0][3], h2, l2);
        bf_split2(cs[1][2], cs[1][3], h3, l3);
        *(int4*)(fr + ((t + 8) * 2 + 0) * 512) = make_int4((int)h0, (int)h2, (int)l0, (int)l2);
        *(int4*)(fr + ((t + 8) * 2 + 1) * 512) = make_int4((int)h1, (int)h3, (int)l1, (int)l3);
    }
    // (no sync needed: each thread reads back only its own records)

    int sub = 0;
    float d[16][4];
    u32 xh[8][4], xl[8][4];

    // Per-sub protocol (no CTA barriers => warps can skew by up to 2 subs):
    //  - each warp: wait full(sub) [acquire], gemm, lane0 arrives on empty(sub)
    //  - tid0 additionally: relaxed-wait empty(sub) round complete, refill sub+3
#define DO_SUB(GEMM_CALL) do { \
        MBARRIER_WAIT_PARITY(mbf + 8 * (sub % 3), (sub / 3) & 1); \
        GEMM_CALL; \
        if (lane == 0) MBARRIER_ARRIVE(mbe + 8 * (sub % 3)); \
        if (tid == 0 && sub + 3 < NSUB) { \
            MBARRIER_WAIT_PARITY_RELAXED(mbe + 8 * (sub % 3), (sub / 3) & 1); \
            prefetch_sub(ring, mbf, sub + 3); \
        } \
        sub++; \
    } while (0)

#define DO_FF(kbase, isHi) \
    DO_SUB(gemm_ff(ring + (u32)((sub % 3) * SUB_BYTES), fr, (kbase), (isHi), d, lane))
#define DO_X(AH, AL, isHi) \
    DO_SUB(gemm_x(ring + (u32)((sub % 3) * SUB_BYTES), (AH), (AL), (isHi), d, lane))

    // ---- input layer: D = ff @ in_w (K=256), x = sin(OMEGA*(D + in_b)) ----
    zero_d(d);
    DO_FF(0, true);  DO_FF(0, false);
    DO_FF(8, true);  DO_FF(8, false);

#pragma unroll
    for (int s = 0; s < 8; s++) {
#pragma unroll
        for (int p = 0; p < 2; p++) {
            int nt = 2 * s + p;
            int col = 8 * nt + 2 * qc;
            float2 bb = *(const float2*)(in_b + col);
            float v00 = sinf(OMEGA * (d[nt][0] + bb.x));
            float v01 = sinf(OMEGA * (d[nt][1] + bb.y));
            float v10 = sinf(OMEGA * (d[nt][2] + bb.x));
            float v11 = sinf(OMEGA * (d[nt][3] + bb.y));
            bf_split2(v00, v01, xh[s][2 * p],     xl[s][2 * p]);
            bf_split2(v10, v11, xh[s][2 * p + 1], xl[s][2 * p + 1]);
        }
    }

    // ---- residual blocks ----
    for (int l = 0; l < 8; l++) {
        const bool skip = ((l & 1) == 0);
        u32 hh[8][4], hl[8][4];

        // GEMM1: D = x @ w1_l ; h = tanh(D + b1_l)
        zero_d(d);
        DO_X(xh, xl, true);  DO_X(xh, xl, false);
#pragma unroll
        for (int s = 0; s < 8; s++) {
#pragma unroll
            for (int p = 0; p < 2; p++) {
                int nt = 2 * s + p;
                int col = 8 * nt + 2 * qc;
                float2 bb = *(const float2*)(b1 + l * 128 + col);
                float v00 = tanhf(d[nt][0] + bb.x);
                float v01 = tanhf(d[nt][1] + bb.y);
                float v10 = tanhf(d[nt][2] + bb.x);
                float v11 = tanhf(d[nt][3] + bb.y);
                bf_split2(v00, v01, hh[s][2 * p],     hl[s][2 * p]);
                bf_split2(v10, v11, hh[s][2 * p + 1], hl[s][2 * p + 1]);
            }
        }

        // GEMM2: D = h @ w2_l (+ ff @ skip_w[l/2])
        zero_d(d);
        DO_X(hh, hl, true);  DO_X(hh, hl, false);
        if (skip) {
            DO_FF(0, true);  DO_FF(0, false);
            DO_FF(8, true);  DO_FF(8, false);
        }

        // epilogue2: x = x + D + b2 (+ skb); re-split into frags
#pragma unroll
        for (int s = 0; s < 8; s++) {
#pragma unroll
            for (int p = 0; p < 2; p++) {
                int nt = 2 * s + p;
                int col = 8 * nt + 2 * qc;
                float2 bb = *(const float2*)(b2 + l * 128 + col);
                float sbx = 0.0f, sby = 0.0f;
                if (skip) {
                    float2 sv = *(const float2*)(skb + (l >> 1) * 128 + col);
                    sbx = sv.x; sby = sv.y;
                }
                int i0 = 2 * p, i1 = 2 * p + 1;
                float v00 = bflo(xh[s][i0]) + bflo(xl[s][i0]) + d[nt][0] + bb.x + sbx;
                float v01 = bfhi(xh[s][i0]) + bfhi(xl[s][i0]) + d[nt][1] + bb.y + sby;
                float v10 = bflo(xh[s][i1]) + bflo(xl[s][i1]) + d[nt][2] + bb.x + sbx;
                float v11 = bfhi(xh[s][i1]) + bfhi(xl[s][i1]) + d[nt][3] + bb.y + sby;
                bf_split2(v00, v01, xh[s][i0], xl[s][i0]);
                bf_split2(v10, v11, xh[s][i1], xl[s][i1]);
            }
        }
    }

    // ---- output layer: out = x @ out_w + out_b ----
    float a0 = 0.0f, a1 = 0.0f;
#pragma unroll
    for (int s = 0; s < 8; s++) {
#pragma unroll
        for (int p = 0; p < 2; p++) {
            int nt = 2 * s + p;
            int col = 8 * nt + 2 * qc;
            float w0 = ows[col], w1v = ows[col + 1];
            int i0 = 2 * p, i1 = 2 * p + 1;
            a0 += (bflo(xh[s][i0]) + bflo(xl[s][i0])) * w0
                + (bfhi(xh[s][i0]) + bfhi(xl[s][i0])) * w1v;
            a1 += (bflo(xh[s][i1]) + bflo(xl[s][i1])) * w0
                + (bfhi(xh[s][i1]) + bfhi(xl[s][i1])) * w1v;
        }
    }
    a0 += __shfl_xor_sync(0xFFFFFFFF, a0, 1);
    a0 += __shfl_xor_sync(0xFFFFFFFF, a0, 2);
    a1 += __shfl_xor_sync(0xFFFFFFFF, a1, 1);
    a1 += __shfl_xor_sync(0xFFFFFFFF, a1, 2);
    if (qc == 0) {
        float obv = ob[0];
        if (r0g < N) out[r0g] = a0 + obv;
        if (r1g < N) out[r1g] = a1 + obv;
    }
#undef DO_FF
#undef DO_X
#undef DO_SUB
}

// ==================== launcher ====================

extern "C" void kernel_launch(void* const* d_in, const int* in_sizes, int n_in,
                              void* d_out, int out_size) {
    const float* S    = (const float*)d_in[0];
    const float* T    = (const float*)d_in[1];
    const float* B    = (const float*)d_in[2];
    const float* in_w = (const float*)d_in[3];
    const float* in_b = (const float*)d_in[4];
    const float* w1   = (const float*)d_in[5];
    const float* b1   = (const float*)d_in[6];
    const float* w2   = (const float*)d_in[7];
    const float* b2   = (const float*)d_in[8];
    const float* skw  = (const float*)d_in[9];
    const float* skb  = (const float*)d_in[10];
    const float* ow   = (const float*)d_in[11];
    const float* ob   = (const float*)d_in[12];
    float* out        = (float*)d_out;

    int N = in_sizes[0];

    convert_weights<<<(26 * 16384 + 255) / 256, 256>>>(in_w, w1, w2, skw);

    cudaFuncSetAttribute(pinn_mma, cudaFuncAttributeMaxDynamicSharedMemorySize, SMEM_BYTES);
    int grid = (N + MT - 1) / MT;
    pinn_mma<<<grid, THREADS, SMEM_BYTES>>>(S, T, B, in_b, b1, b2, skb, ow, ob, out, N);
}